// round 12
// baseline (speedup 1.0000x reference)
#include <cuda_runtime.h>

#define B_   32
#define C_   3072
#define K_   11
#define HW_  784
#define NC_  200

// d_out layout: [afm (B,C,K)][scores (B,NC)][maps (B,K,HW)][attn (B,K)]
#define OFF_SCORES 1081344
#define OFF_MAPS   1087744
#define OFF_ATTN   1363712

__device__ float g_asq[16];
__device__ float g_f[B_ * C_];

typedef unsigned long long u64;

__device__ __forceinline__ u64 pk(float a, float b) {
    u64 r; asm("mov.b64 %0,{%1,%2};" : "=l"(r) : "f"(a), "f"(b)); return r;
}
__device__ __forceinline__ float2 upk(u64 a) {
    float2 f; asm("mov.b64 {%0,%1},%2;" : "=f"(f.x), "=f"(f.y) : "l"(a)); return f;
}
__device__ __forceinline__ void fma2(u64& d, u64 a, u64 b) {
    asm("fma.rn.f32x2 %0,%1,%2,%0;" : "+l"(d) : "l"(a), "l"(b));
}
__device__ __forceinline__ u64 add2(u64 a, u64 b) {
    u64 r; asm("add.rn.f32x2 %0,%1,%2;" : "=l"(r) : "l"(a), "l"(b)); return r;
}

// ---------------------------------------------------------------------------
// a_sq[k] = sum_c w_land[k,c]^2  (block per k)
// ---------------------------------------------------------------------------
__global__ void asq_kernel(const float* __restrict__ wl) {
    __shared__ float red[8];
    int k = blockIdx.x;
    const float* row = wl + k * C_;
    float s = 0.f;
    for (int c = threadIdx.x; c < C_; c += 256) { float v = row[c]; s = fmaf(v, v, s); }
    int warp = threadIdx.x >> 5, lane = threadIdx.x & 31;
    #pragma unroll
    for (int o = 16; o; o >>= 1) s += __shfl_xor_sync(0xffffffffu, s, o);
    if (lane == 0) red[warp] = s;
    __syncthreads();
    if (threadIdx.x == 0) {
        float t = 0.f;
        #pragma unroll
        for (int w = 0; w < 8; w++) t += red[w];
        g_asq[k] = t;
    }
}

__global__ void dummy_kernel() {}

// ---------------------------------------------------------------------------
// maps kernel v5 (proven ~87us): w resident (147KB smem), persistent 148x512,
// thread = 4 contiguous pixels (LDG.128) x 96-ch segment, unroll 4.
// ---------------------------------------------------------------------------
#define MTILES 392
__global__ __launch_bounds__(512, 1) void maps_kernel(
    const float* __restrict__ x, const float* __restrict__ wl,
    float* __restrict__ maps)
{
    extern __shared__ __align__(16) float smem[];
    float*  sw  = smem;                       // [3072][12] padded
    float2* red = (float2*)(smem + C_ * 12);  // [16 segpair][64 px][6 pairs]
    int tid    = threadIdx.x;
    int lane   = tid & 31;
    int lane16 = tid & 15;
    int warp   = tid >> 5;
    int seg    = tid >> 4;                    // 0..31, 96 channels each

    #pragma unroll 1
    for (int k = 0; k < K_; k++)
        for (int c = tid; c < C_; c += 512)
            sw[c * 12 + k] = wl[k * C_ + c];
    for (int c = tid; c < C_; c += 512) sw[c * 12 + 11] = 0.f;
    __syncthreads();

    const int cbase = seg * 96;
    #pragma unroll 1
    for (int tile = blockIdx.x; tile < MTILES; tile += gridDim.x) {
        int q   = tile * 16 + lane16;
        int b   = q / 196;
        int hw0 = (q - b * 196) * 4;
        const float* xp = x + (size_t)b * (C_ * HW_) + hw0;

        u64 acc[4][6];
        #pragma unroll
        for (int p = 0; p < 4; p++)
            #pragma unroll
            for (int j = 0; j < 6; j++) acc[p][j] = 0ull;

        #pragma unroll 4
        for (int i = 0; i < 96; i++) {
            int c = cbase + i;
            float4 xv = *(const float4*)(xp + (size_t)c * HW_);
            const u64* wp = (const u64*)(sw + c * 12);
            u64 x0 = pk(xv.x, xv.x);
            u64 x1 = pk(xv.y, xv.y);
            u64 x2 = pk(xv.z, xv.z);
            u64 x3 = pk(xv.w, xv.w);
            #pragma unroll
            for (int j = 0; j < 6; j++) {
                u64 w2 = wp[j];
                fma2(acc[0][j], x0, w2);
                fma2(acc[1][j], x1, w2);
                fma2(acc[2][j], x2, w2);
                fma2(acc[3][j], x3, w2);
            }
        }

        #pragma unroll
        for (int p = 0; p < 4; p++)
            #pragma unroll
            for (int j = 0; j < 6; j++)
                acc[p][j] = add2(acc[p][j],
                                 __shfl_xor_sync(0xffffffffu, acc[p][j], 16));
        if (lane < 16) {
            #pragma unroll
            for (int p = 0; p < 4; p++)
                #pragma unroll
                for (int j = 0; j < 6; j++)
                    red[(warp * 64 + lane16 * 4 + p) * 6 + j] = upk(acc[p][j]);
        }
        __syncthreads();

        if (tid < 64) {
            float lg[12];
            #pragma unroll
            for (int k = 0; k < 12; k++) lg[k] = 0.f;
            #pragma unroll 4
            for (int s = 0; s < 16; s++) {
                #pragma unroll
                for (int j = 0; j < 6; j++) {
                    float2 v = red[(s * 64 + tid) * 6 + j];
                    lg[2 * j]     += v.x;
                    lg[2 * j + 1] += v.y;
                }
            }
            float m = -1e30f;
            #pragma unroll
            for (int k = 0; k < K_; k++) {
                lg[k] = 2.f * lg[k] - g_asq[k];
                m = fmaxf(m, lg[k]);
            }
            float s = 0.f;
            #pragma unroll
            for (int k = 0; k < K_; k++) { lg[k] = __expf(lg[k] - m); s += lg[k]; }
            float inv = 1.f / s;
            int g2  = tile * 64 + tid;
            int b2  = g2 / HW_;
            int hw  = g2 - b2 * HW_;
            float* mp = maps + (size_t)b2 * (K_ * HW_) + hw;
            #pragma unroll
            for (int k = 0; k < K_; k++) mp[k * HW_] = lg[k] * inv;
        }
        __syncthreads();
    }
}

// ---------------------------------------------------------------------------
// feature kernel v10: 3 channels share each maps LDS.128; scalar acc (33 regs)
// keeps 3 blocks/SM. grid (32, B): block = 96 ch, 8 warps x 4 triples.
// ---------------------------------------------------------------------------
__global__ __launch_bounds__(256, 3) void feat_kernel(
    const float* __restrict__ x, const float* __restrict__ maps,
    const float* __restrict__ mod, float* __restrict__ afm,
    float* __restrict__ attn)
{
    __shared__ __align__(16) float sm[K_ * 800];   // 35200 B
    int b = blockIdx.y;
    const float* mp = maps + (size_t)b * (K_ * HW_);
    for (int idx = threadIdx.x; idx < K_ * HW_; idx += 256) {
        int k  = idx / HW_;
        int hw = idx - k * HW_;
        sm[k * 800 + hw] = mp[idx];
    }
    __syncthreads();
    int warp = threadIdx.x >> 5, lane = threadIdx.x & 31;

    if (blockIdx.x == 0) {   // attn folded in
        for (int k = warp; k < K_; k += 8) {
            float s = 0.f;
            for (int hw = lane; hw < HW_; hw += 32) s += sm[k * 800 + hw];
            #pragma unroll
            for (int o = 16; o; o >>= 1) s += __shfl_xor_sync(0xffffffffu, s, o);
            if (lane == 0) attn[b * K_ + k] = s;
        }
    }

    #pragma unroll 1
    for (int g = 0; g < 4; g++) {
        int c0 = blockIdx.x * 96 + warp * 12 + g * 3;
        const float* xp0 = x + ((size_t)b * C_ + c0) * HW_;
        const float* xp1 = xp0 + HW_;
        const float* xp2 = xp1 + HW_;
        float s0[K_], s1[K_], s2[K_];
        #pragma unroll
        for (int k = 0; k < K_; k++) { s0[k] = 0.f; s1[k] = 0.f; s2[k] = 0.f; }

        #pragma unroll 1
        for (int i = 0; i < 7; i++) {
            int hw = i * 128 + lane * 4;
            if (hw < HW_) {
                float4 x0 = *(const float4*)(xp0 + hw);
                float4 x1 = *(const float4*)(xp1 + hw);
                float4 x2 = *(const float4*)(xp2 + hw);
                #pragma unroll
                for (int k = 0; k < K_; k++) {
                    float4 mv = *(const float4*)(sm + k * 800 + hw);
                    s0[k] = fmaf(x0.x, mv.x, s0[k]);
                    s0[k] = fmaf(x0.y, mv.y, s0[k]);
                    s0[k] = fmaf(x0.z, mv.z, s0[k]);
                    s0[k] = fmaf(x0.w, mv.w, s0[k]);
                    s1[k] = fmaf(x1.x, mv.x, s1[k]);
                    s1[k] = fmaf(x1.y, mv.y, s1[k]);
                    s1[k] = fmaf(x1.z, mv.z, s1[k]);
                    s1[k] = fmaf(x1.w, mv.w, s1[k]);
                    s2[k] = fmaf(x2.x, mv.x, s2[k]);
                    s2[k] = fmaf(x2.y, mv.y, s2[k]);
                    s2[k] = fmaf(x2.z, mv.z, s2[k]);
                    s2[k] = fmaf(x2.w, mv.w, s2[k]);
                }
            }
        }

        #pragma unroll
        for (int k = 0; k < K_; k++) {
            #pragma unroll
            for (int o = 16; o; o >>= 1) {
                s0[k] += __shfl_xor_sync(0xffffffffu, s0[k], o);
                s1[k] += __shfl_xor_sync(0xffffffffu, s1[k], o);
                s2[k] += __shfl_xor_sync(0xffffffffu, s2[k], o);
            }
        }
        if (lane == 0) {
            const float inv = 1.f / (float)HW_;
            float f0 = 0.f, f1 = 0.f, f2 = 0.f;
            float* o0 = afm + ((size_t)b * C_ + c0) * K_;
            #pragma unroll
            for (int k = 0; k < K_; k++) {
                float v0 = s0[k] * inv * mod[c0 * K_ + k];
                float v1 = s1[k] * inv * mod[(c0 + 1) * K_ + k];
                float v2 = s2[k] * inv * mod[(c0 + 2) * K_ + k];
                o0[k]          = v0;
                o0[K_ + k]     = v1;
                o0[2 * K_ + k] = v2;
                f0 += v0;
                f1 += v1;
                f2 += v2;
            }
            g_f[b * C_ + c0]     = f0;
            g_f[b * C_ + c0 + 1] = f1;
            g_f[b * C_ + c0 + 2] = f2;
        }
    }
}

// ---------------------------------------------------------------------------
// scores[b,n] = sum_c f[b,c] * w_cls[n,c]; grid (25, B), warp per n.
// ---------------------------------------------------------------------------
__global__ __launch_bounds__(256) void score_kernel(
    const float* __restrict__ wcls, float* __restrict__ scores)
{
    __shared__ __align__(16) float sf[C_];
    int b = blockIdx.y;
    for (int idx = threadIdx.x; idx < C_; idx += 256) sf[idx] = g_f[b * C_ + idx];
    __syncthreads();
    int warp = threadIdx.x >> 5, lane = threadIdx.x & 31;
    int n = blockIdx.x * 8 + warp;
    const float* wr = wcls + (size_t)n * C_;
    float s = 0.f;
    #pragma unroll 6
    for (int c = lane * 4; c < C_; c += 128) {
        float4 wv = *(const float4*)(wr + c);
        float4 fv = *(const float4*)(sf + c);
        s = fmaf(wv.x, fv.x, s);
        s = fmaf(wv.y, fv.y, s);
        s = fmaf(wv.z, fv.z, s);
        s = fmaf(wv.w, fv.w, s);
    }
    #pragma unroll
    for (int o = 16; o; o >>= 1) s += __shfl_xor_sync(0xffffffffu, s, o);
    if (lane == 0) scores[b * NC_ + n] = s;
}

// ---------------------------------------------------------------------------
extern "C" void kernel_launch(void* const* d_in, const int* in_sizes, int n_in,
                              void* d_out, int out_size) {
    const float* x    = (const float*)d_in[0];   // (B,C,H,W)
    const float* wl   = (const float*)d_in[1];   // (K,C)
    const float* mod  = (const float*)d_in[2];   // (1,C,K)
    const float* wcls = (const float*)d_in[3];   // (NC,C)
    float* out    = (float*)d_out;
    float* afm    = out;
    float* scores = out + OFF_SCORES;
    float* maps   = out + OFF_MAPS;
    float* attn   = out + OFF_ATTN;

    const int MAPS_SMEM = (C_ * 12 + 16 * 64 * 6 * 2) * 4;   // 196608 B
    cudaFuncSetAttribute(maps_kernel,
                         cudaFuncAttributeMaxDynamicSharedMemorySize, MAPS_SMEM);

    asq_kernel<<<K_, 256>>>(wl);
    dummy_kernel<<<1, 32>>>();
    maps_kernel<<<148, 512, MAPS_SMEM>>>(x, wl, maps);
    feat_kernel<<<dim3(32, B_), 256>>>(x, maps, mod, afm, attn);  // launch #4 -> profiled
    score_kernel<<<dim3(25, B_), 256>>>(wcls, scores);
}

// round 13
// speedup vs baseline: 1.1665x; 1.1665x over previous
#include <cuda_runtime.h>

#define B_   32
#define C_   3072
#define K_   11
#define HW_  784
#define NC_  200

// d_out layout: [afm (B,C,K)][scores (B,NC)][maps (B,K,HW)][attn (B,K)]
#define OFF_SCORES 1081344
#define OFF_MAPS   1087744
#define OFF_ATTN   1363712

__device__ float g_asq[16];
__device__ float g_f[B_ * C_];

typedef unsigned long long u64;

__device__ __forceinline__ u64 pk(float a, float b) {
    u64 r; asm("mov.b64 %0,{%1,%2};" : "=l"(r) : "f"(a), "f"(b)); return r;
}
__device__ __forceinline__ float2 upk(u64 a) {
    float2 f; asm("mov.b64 {%0,%1},%2;" : "=f"(f.x), "=f"(f.y) : "l"(a)); return f;
}
__device__ __forceinline__ void fma2(u64& d, u64 a, u64 b) {
    asm("fma.rn.f32x2 %0,%1,%2,%0;" : "+l"(d) : "l"(a), "l"(b));
}
__device__ __forceinline__ u64 add2(u64 a, u64 b) {
    u64 r; asm("add.rn.f32x2 %0,%1,%2;" : "=l"(r) : "l"(a), "l"(b)); return r;
}

// ---------------------------------------------------------------------------
// a_sq[k] = sum_c w_land[k,c]^2  (block per k)
// ---------------------------------------------------------------------------
__global__ void asq_kernel(const float* __restrict__ wl) {
    __shared__ float red[8];
    int k = blockIdx.x;
    const float* row = wl + k * C_;
    float s = 0.f;
    for (int c = threadIdx.x; c < C_; c += 256) { float v = row[c]; s = fmaf(v, v, s); }
    int warp = threadIdx.x >> 5, lane = threadIdx.x & 31;
    #pragma unroll
    for (int o = 16; o; o >>= 1) s += __shfl_xor_sync(0xffffffffu, s, o);
    if (lane == 0) red[warp] = s;
    __syncthreads();
    if (threadIdx.x == 0) {
        float t = 0.f;
        #pragma unroll
        for (int w = 0; w < 8; w++) t += red[w];
        g_asq[k] = t;
    }
}

__global__ void dummy_kernel() {}

// ---------------------------------------------------------------------------
// maps kernel v7: 768 threads (24 warps/SM) for better FMA/DRAM overlap.
// w resident (147.5KB) + red 72KB = 216KB smem. Persistent 148 blocks.
// Thread: 4 contiguous pixels (LDG.128) x one of 48 segments (64 ch each).
// Warp = 2 segments folded by shfl-16. k packed in 6 f32x2 pairs.
// ---------------------------------------------------------------------------
#define MTILES 392
#define MWARPS 24
__global__ __launch_bounds__(768, 1) void maps_kernel(
    const float* __restrict__ x, const float* __restrict__ wl,
    float* __restrict__ maps)
{
    extern __shared__ __align__(16) float smem[];
    float*  sw  = smem;                       // [3072][12] padded
    float2* red = (float2*)(smem + C_ * 12);  // [24 segpair][64 px][6 pairs]
    int tid    = threadIdx.x;
    int lane   = tid & 31;
    int lane16 = tid & 15;
    int warp   = tid >> 5;                    // 0..23
    int seg    = tid >> 4;                    // 0..47, 64 channels each

    #pragma unroll 1
    for (int k = 0; k < K_; k++)
        for (int c = tid; c < C_; c += 768)
            sw[c * 12 + k] = wl[k * C_ + c];
    for (int c = tid; c < C_; c += 768) sw[c * 12 + 11] = 0.f;
    __syncthreads();

    const int cbase = seg * 64;
    #pragma unroll 1
    for (int tile = blockIdx.x; tile < MTILES; tile += gridDim.x) {
        int q   = tile * 16 + lane16;
        int b   = q / 196;
        int hw0 = (q - b * 196) * 4;
        const float* xp = x + (size_t)b * (C_ * HW_) + hw0;

        u64 acc[4][6];
        #pragma unroll
        for (int p = 0; p < 4; p++)
            #pragma unroll
            for (int j = 0; j < 6; j++) acc[p][j] = 0ull;

        #pragma unroll 4
        for (int i = 0; i < 64; i++) {
            int c = cbase + i;
            float4 xv = *(const float4*)(xp + (size_t)c * HW_);
            const u64* wp = (const u64*)(sw + c * 12);
            u64 x0 = pk(xv.x, xv.x);
            u64 x1 = pk(xv.y, xv.y);
            u64 x2 = pk(xv.z, xv.z);
            u64 x3 = pk(xv.w, xv.w);
            #pragma unroll
            for (int j = 0; j < 6; j++) {
                u64 w2 = wp[j];
                fma2(acc[0][j], x0, w2);
                fma2(acc[1][j], x1, w2);
                fma2(acc[2][j], x2, w2);
                fma2(acc[3][j], x3, w2);
            }
        }

        // fold the two segments sharing this warp
        #pragma unroll
        for (int p = 0; p < 4; p++)
            #pragma unroll
            for (int j = 0; j < 6; j++)
                acc[p][j] = add2(acc[p][j],
                                 __shfl_xor_sync(0xffffffffu, acc[p][j], 16));
        if (lane < 16) {
            #pragma unroll
            for (int p = 0; p < 4; p++)
                #pragma unroll
                for (int j = 0; j < 6; j++)
                    red[(warp * 64 + lane16 * 4 + p) * 6 + j] = upk(acc[p][j]);
        }
        __syncthreads();

        if (tid < 64) {
            float lg[12];
            #pragma unroll
            for (int k = 0; k < 12; k++) lg[k] = 0.f;
            #pragma unroll 4
            for (int s = 0; s < MWARPS; s++) {
                #pragma unroll
                for (int j = 0; j < 6; j++) {
                    float2 v = red[(s * 64 + tid) * 6 + j];
                    lg[2 * j]     += v.x;
                    lg[2 * j + 1] += v.y;
                }
            }
            float m = -1e30f;
            #pragma unroll
            for (int k = 0; k < K_; k++) {
                lg[k] = 2.f * lg[k] - g_asq[k];
                m = fmaxf(m, lg[k]);
            }
            float s = 0.f;
            #pragma unroll
            for (int k = 0; k < K_; k++) { lg[k] = __expf(lg[k] - m); s += lg[k]; }
            float inv = 1.f / s;
            int g2  = tile * 64 + tid;
            int b2  = g2 / HW_;
            int hw  = g2 - b2 * HW_;
            float* mp = maps + (size_t)b2 * (K_ * HW_) + hw;
            #pragma unroll
            for (int k = 0; k < K_; k++) mp[k * HW_] = lg[k] * inv;
        }
        __syncthreads();
    }
}

// ---------------------------------------------------------------------------
// feature kernel v9 (best measured 124.1us): scalar float accumulators,
// grid (24, B): 8 warps x 8 pairs of channels; lanes span HW (float4);
// maps tile k-major in smem (LDS.128); 3 blocks/SM.
// ---------------------------------------------------------------------------
__global__ __launch_bounds__(256, 3) void feat_kernel(
    const float* __restrict__ x, const float* __restrict__ maps,
    const float* __restrict__ mod, float* __restrict__ afm,
    float* __restrict__ attn)
{
    __shared__ __align__(16) float sm[K_ * 800];   // 35200 B
    int b = blockIdx.y;
    const float* mp = maps + (size_t)b * (K_ * HW_);
    for (int idx = threadIdx.x; idx < K_ * HW_; idx += 256) {
        int k  = idx / HW_;
        int hw = idx - k * HW_;
        sm[k * 800 + hw] = mp[idx];
    }
    __syncthreads();
    int warp = threadIdx.x >> 5, lane = threadIdx.x & 31;

    if (blockIdx.x == 0) {   // attn folded in
        for (int k = warp; k < K_; k += 8) {
            float s = 0.f;
            for (int hw = lane; hw < HW_; hw += 32) s += sm[k * 800 + hw];
            #pragma unroll
            for (int o = 16; o; o >>= 1) s += __shfl_xor_sync(0xffffffffu, s, o);
            if (lane == 0) attn[b * K_ + k] = s;
        }
    }

    #pragma unroll 1
    for (int pair = 0; pair < 8; pair++) {
        int c0 = blockIdx.x * 128 + warp * 16 + pair * 2;
        const float* xp0 = x + ((size_t)b * C_ + c0) * HW_;
        const float* xp1 = xp0 + HW_;
        float s0[K_], s1[K_];
        #pragma unroll
        for (int k = 0; k < K_; k++) { s0[k] = 0.f; s1[k] = 0.f; }

        #pragma unroll 1
        for (int i = 0; i < 7; i++) {
            int hw = i * 128 + lane * 4;
            if (hw < HW_) {
                float4 x0 = *(const float4*)(xp0 + hw);
                float4 x1 = *(const float4*)(xp1 + hw);
                #pragma unroll
                for (int k = 0; k < K_; k++) {
                    float4 mv = *(const float4*)(sm + k * 800 + hw);
                    s0[k] = fmaf(x0.x, mv.x, s0[k]);
                    s0[k] = fmaf(x0.y, mv.y, s0[k]);
                    s0[k] = fmaf(x0.z, mv.z, s0[k]);
                    s0[k] = fmaf(x0.w, mv.w, s0[k]);
                    s1[k] = fmaf(x1.x, mv.x, s1[k]);
                    s1[k] = fmaf(x1.y, mv.y, s1[k]);
                    s1[k] = fmaf(x1.z, mv.z, s1[k]);
                    s1[k] = fmaf(x1.w, mv.w, s1[k]);
                }
            }
        }

        #pragma unroll
        for (int k = 0; k < K_; k++) {
            #pragma unroll
            for (int o = 16; o; o >>= 1) {
                s0[k] += __shfl_xor_sync(0xffffffffu, s0[k], o);
                s1[k] += __shfl_xor_sync(0xffffffffu, s1[k], o);
            }
        }
        if (lane == 0) {
            const float inv = 1.f / (float)HW_;
            float f0 = 0.f, f1 = 0.f;
            float* o0 = afm + ((size_t)b * C_ + c0) * K_;
            #pragma unroll
            for (int k = 0; k < K_; k++) {
                float v0 = s0[k] * inv * mod[c0 * K_ + k];
                float v1 = s1[k] * inv * mod[(c0 + 1) * K_ + k];
                o0[k]      = v0;
                o0[K_ + k] = v1;
                f0 += v0;
                f1 += v1;
            }
            g_f[b * C_ + c0]     = f0;
            g_f[b * C_ + c0 + 1] = f1;
        }
    }
}

// ---------------------------------------------------------------------------
// scores[b,n] = sum_c f[b,c] * w_cls[n,c]; grid (25, B), warp per n.
// ---------------------------------------------------------------------------
__global__ __launch_bounds__(256) void score_kernel(
    const float* __restrict__ wcls, float* __restrict__ scores)
{
    __shared__ __align__(16) float sf[C_];
    int b = blockIdx.y;
    for (int idx = threadIdx.x; idx < C_; idx += 256) sf[idx] = g_f[b * C_ + idx];
    __syncthreads();
    int warp = threadIdx.x >> 5, lane = threadIdx.x & 31;
    int n = blockIdx.x * 8 + warp;
    const float* wr = wcls + (size_t)n * C_;
    float s = 0.f;
    #pragma unroll 6
    for (int c = lane * 4; c < C_; c += 128) {
        float4 wv = *(const float4*)(wr + c);
        float4 fv = *(const float4*)(sf + c);
        s = fmaf(wv.x, fv.x, s);
        s = fmaf(wv.y, fv.y, s);
        s = fmaf(wv.z, fv.z, s);
        s = fmaf(wv.w, fv.w, s);
    }
    #pragma unroll
    for (int o = 16; o; o >>= 1) s += __shfl_xor_sync(0xffffffffu, s, o);
    if (lane == 0) scores[b * NC_ + n] = s;
}

// ---------------------------------------------------------------------------
extern "C" void kernel_launch(void* const* d_in, const int* in_sizes, int n_in,
                              void* d_out, int out_size) {
    const float* x    = (const float*)d_in[0];   // (B,C,H,W)
    const float* wl   = (const float*)d_in[1];   // (K,C)
    const float* mod  = (const float*)d_in[2];   // (1,C,K)
    const float* wcls = (const float*)d_in[3];   // (NC,C)
    float* out    = (float*)d_out;
    float* afm    = out;
    float* scores = out + OFF_SCORES;
    float* maps   = out + OFF_MAPS;
    float* attn   = out + OFF_ATTN;

    const int MAPS_SMEM = (C_ * 12 + MWARPS * 64 * 6 * 2) * 4;   // 221184 B
    cudaFuncSetAttribute(maps_kernel,
                         cudaFuncAttributeMaxDynamicSharedMemorySize, MAPS_SMEM);

    asq_kernel<<<K_, 256>>>(wl);
    dummy_kernel<<<1, 32>>>();
    dummy_kernel<<<1, 32>>>();                   // maps -> launch #4 (profiled)
    maps_kernel<<<148, 768, MAPS_SMEM>>>(x, wl, maps);
    feat_kernel<<<dim3(24, B_), 256>>>(x, maps, mod, afm, attn);
    score_kernel<<<dim3(25, B_), 256>>>(wcls, scores);
}

// round 14
// speedup vs baseline: 1.2836x; 1.1004x over previous
#include <cuda_runtime.h>

#define B_   32
#define C_   3072
#define K_   11
#define HW_  784
#define NC_  200

// d_out layout: [afm (B,C,K)][scores (B,NC)][maps (B,K,HW)][attn (B,K)]
#define OFF_SCORES 1081344
#define OFF_MAPS   1087744
#define OFF_ATTN   1363712

__device__ float g_asq[16];
__device__ float g_f[B_ * C_];

typedef unsigned long long u64;

__device__ __forceinline__ u64 pk(float a, float b) {
    u64 r; asm("mov.b64 %0,{%1,%2};" : "=l"(r) : "f"(a), "f"(b)); return r;
}
__device__ __forceinline__ float2 upk(u64 a) {
    float2 f; asm("mov.b64 {%0,%1},%2;" : "=f"(f.x), "=f"(f.y) : "l"(a)); return f;
}
__device__ __forceinline__ void fma2(u64& d, u64 a, u64 b) {
    asm("fma.rn.f32x2 %0,%1,%2,%0;" : "+l"(d) : "l"(a), "l"(b));
}
__device__ __forceinline__ u64 add2(u64 a, u64 b) {
    u64 r; asm("add.rn.f32x2 %0,%1,%2;" : "=l"(r) : "l"(a), "l"(b)); return r;
}

// ---------------------------------------------------------------------------
// a_sq[k] = sum_c w_land[k,c]^2  (block per k)
// ---------------------------------------------------------------------------
__global__ void asq_kernel(const float* __restrict__ wl) {
    __shared__ float red[8];
    int k = blockIdx.x;
    const float* row = wl + k * C_;
    float s = 0.f;
    for (int c = threadIdx.x; c < C_; c += 256) { float v = row[c]; s = fmaf(v, v, s); }
    int warp = threadIdx.x >> 5, lane = threadIdx.x & 31;
    #pragma unroll
    for (int o = 16; o; o >>= 1) s += __shfl_xor_sync(0xffffffffu, s, o);
    if (lane == 0) red[warp] = s;
    __syncthreads();
    if (threadIdx.x == 0) {
        float t = 0.f;
        #pragma unroll
        for (int w = 0; w < 8; w++) t += red[w];
        g_asq[k] = t;
    }
}

__global__ void dummy_kernel() {}

// ---------------------------------------------------------------------------
// maps kernel v5 (proven ~87us): w resident (147KB smem), persistent 148x512,
// thread = 4 contiguous pixels (LDG.128) x one of 32 segments (96 ch),
// warp = 2 segments folded by shfl-16, unroll 4.
// ---------------------------------------------------------------------------
#define MTILES 392
__global__ __launch_bounds__(512, 1) void maps_kernel(
    const float* __restrict__ x, const float* __restrict__ wl,
    float* __restrict__ maps)
{
    extern __shared__ __align__(16) float smem[];
    float*  sw  = smem;                       // [3072][12] padded
    float2* red = (float2*)(smem + C_ * 12);  // [16 segpair][64 px][6 pairs]
    int tid    = threadIdx.x;
    int lane   = tid & 31;
    int lane16 = tid & 15;
    int warp   = tid >> 5;
    int seg    = tid >> 4;                    // 0..31, 96 channels each

    #pragma unroll 1
    for (int k = 0; k < K_; k++)
        for (int c = tid; c < C_; c += 512)
            sw[c * 12 + k] = wl[k * C_ + c];
    for (int c = tid; c < C_; c += 512) sw[c * 12 + 11] = 0.f;
    __syncthreads();

    const int cbase = seg * 96;
    #pragma unroll 1
    for (int tile = blockIdx.x; tile < MTILES; tile += gridDim.x) {
        int q   = tile * 16 + lane16;
        int b   = q / 196;
        int hw0 = (q - b * 196) * 4;
        const float* xp = x + (size_t)b * (C_ * HW_) + hw0;

        u64 acc[4][6];
        #pragma unroll
        for (int p = 0; p < 4; p++)
            #pragma unroll
            for (int j = 0; j < 6; j++) acc[p][j] = 0ull;

        #pragma unroll 4
        for (int i = 0; i < 96; i++) {
            int c = cbase + i;
            float4 xv = *(const float4*)(xp + (size_t)c * HW_);
            const u64* wp = (const u64*)(sw + c * 12);
            u64 x0 = pk(xv.x, xv.x);
            u64 x1 = pk(xv.y, xv.y);
            u64 x2 = pk(xv.z, xv.z);
            u64 x3 = pk(xv.w, xv.w);
            #pragma unroll
            for (int j = 0; j < 6; j++) {
                u64 w2 = wp[j];
                fma2(acc[0][j], x0, w2);
                fma2(acc[1][j], x1, w2);
                fma2(acc[2][j], x2, w2);
                fma2(acc[3][j], x3, w2);
            }
        }

        #pragma unroll
        for (int p = 0; p < 4; p++)
            #pragma unroll
            for (int j = 0; j < 6; j++)
                acc[p][j] = add2(acc[p][j],
                                 __shfl_xor_sync(0xffffffffu, acc[p][j], 16));
        if (lane < 16) {
            #pragma unroll
            for (int p = 0; p < 4; p++)
                #pragma unroll
                for (int j = 0; j < 6; j++)
                    red[(warp * 64 + lane16 * 4 + p) * 6 + j] = upk(acc[p][j]);
        }
        __syncthreads();

        if (tid < 64) {
            float lg[12];
            #pragma unroll
            for (int k = 0; k < 12; k++) lg[k] = 0.f;
            #pragma unroll 4
            for (int s = 0; s < 16; s++) {
                #pragma unroll
                for (int j = 0; j < 6; j++) {
                    float2 v = red[(s * 64 + tid) * 6 + j];
                    lg[2 * j]     += v.x;
                    lg[2 * j + 1] += v.y;
                }
            }
            float m = -1e30f;
            #pragma unroll
            for (int k = 0; k < K_; k++) {
                lg[k] = 2.f * lg[k] - g_asq[k];
                m = fmaxf(m, lg[k]);
            }
            float s = 0.f;
            #pragma unroll
            for (int k = 0; k < K_; k++) { lg[k] = __expf(lg[k] - m); s += lg[k]; }
            float inv = 1.f / s;
            int g2  = tile * 64 + tid;
            int b2  = g2 / HW_;
            int hw  = g2 - b2 * HW_;
            float* mp = maps + (size_t)b2 * (K_ * HW_) + hw;
            #pragma unroll
            for (int k = 0; k < K_; k++) mp[k * HW_] = lg[k] * inv;
        }
        __syncthreads();
    }
}

// ---------------------------------------------------------------------------
// feature kernel v11 = v9 core + lane-parallel epilogue.
// grid (24, B): 8 warps x 8 pairs of channels; lanes span HW (float4);
// maps tile k-major in smem; 3 blocks/SM. After the butterfly reduce every
// lane holds all sums, so lanes 0-10 handle (ch0,k) and 16-26 handle (ch1,k):
// parallel mod-load/mul/store, then a 4-round half-warp reduce for g_f.
// ---------------------------------------------------------------------------
__global__ __launch_bounds__(256, 3) void feat_kernel(
    const float* __restrict__ x, const float* __restrict__ maps,
    const float* __restrict__ mod, float* __restrict__ afm,
    float* __restrict__ attn)
{
    __shared__ __align__(16) float sm[K_ * 800];   // 35200 B
    int b = blockIdx.y;
    const float* mp = maps + (size_t)b * (K_ * HW_);
    for (int idx = threadIdx.x; idx < K_ * HW_; idx += 256) {
        int k  = idx / HW_;
        int hw = idx - k * HW_;
        sm[k * 800 + hw] = mp[idx];
    }
    __syncthreads();
    int warp = threadIdx.x >> 5, lane = threadIdx.x & 31;
    int half = lane >> 4;          // 0: ch0, 1: ch1
    int kidx = lane & 15;          // k slot (active if < 11)

    if (blockIdx.x == 0) {   // attn folded in
        for (int k = warp; k < K_; k += 8) {
            float s = 0.f;
            for (int hw = lane; hw < HW_; hw += 32) s += sm[k * 800 + hw];
            #pragma unroll
            for (int o = 16; o; o >>= 1) s += __shfl_xor_sync(0xffffffffu, s, o);
            if (lane == 0) attn[b * K_ + k] = s;
        }
    }

    #pragma unroll 1
    for (int pair = 0; pair < 8; pair++) {
        int c0 = blockIdx.x * 128 + warp * 16 + pair * 2;
        const float* xp0 = x + ((size_t)b * C_ + c0) * HW_;
        const float* xp1 = xp0 + HW_;
        float s0[K_], s1[K_];
        #pragma unroll
        for (int k = 0; k < K_; k++) { s0[k] = 0.f; s1[k] = 0.f; }

        #pragma unroll 1
        for (int i = 0; i < 7; i++) {
            int hw = i * 128 + lane * 4;
            if (hw < HW_) {
                float4 x0 = *(const float4*)(xp0 + hw);
                float4 x1 = *(const float4*)(xp1 + hw);
                #pragma unroll
                for (int k = 0; k < K_; k++) {
                    float4 mv = *(const float4*)(sm + k * 800 + hw);
                    s0[k] = fmaf(x0.x, mv.x, s0[k]);
                    s0[k] = fmaf(x0.y, mv.y, s0[k]);
                    s0[k] = fmaf(x0.z, mv.z, s0[k]);
                    s0[k] = fmaf(x0.w, mv.w, s0[k]);
                    s1[k] = fmaf(x1.x, mv.x, s1[k]);
                    s1[k] = fmaf(x1.y, mv.y, s1[k]);
                    s1[k] = fmaf(x1.z, mv.z, s1[k]);
                    s1[k] = fmaf(x1.w, mv.w, s1[k]);
                }
            }
        }

        #pragma unroll
        for (int k = 0; k < K_; k++) {
            #pragma unroll
            for (int o = 16; o; o >>= 1) {
                s0[k] += __shfl_xor_sync(0xffffffffu, s0[k], o);
                s1[k] += __shfl_xor_sync(0xffffffffu, s1[k], o);
            }
        }

        // lane-parallel epilogue: register-select this lane's (half, kidx) sum
        float v0s = s0[0], v1s = s1[0];
        #pragma unroll
        for (int k = 1; k < K_; k++) {
            v0s = (kidx == k) ? s0[k] : v0s;
            v1s = (kidx == k) ? s1[k] : v1s;
        }
        float val = half ? v1s : v0s;
        float f = 0.f;
        if (kidx < K_) {
            const float inv = 1.f / (float)HW_;
            int c = c0 + half;
            float v = val * inv * mod[c * K_ + kidx];
            afm[((size_t)b * C_ + c) * K_ + kidx] = v;
            f = v;
        }
        #pragma unroll
        for (int o = 8; o; o >>= 1) f += __shfl_xor_sync(0xffffffffu, f, o);
        if (kidx == 0) g_f[b * C_ + c0 + half] = f;
    }
}

// ---------------------------------------------------------------------------
// scores[b,n] = sum_c f[b,c] * w_cls[n,c]; grid (25, B), warp per n.
// ---------------------------------------------------------------------------
__global__ __launch_bounds__(256) void score_kernel(
    const float* __restrict__ wcls, float* __restrict__ scores)
{
    __shared__ __align__(16) float sf[C_];
    int b = blockIdx.y;
    for (int idx = threadIdx.x; idx < C_; idx += 256) sf[idx] = g_f[b * C_ + idx];
    __syncthreads();
    int warp = threadIdx.x >> 5, lane = threadIdx.x & 31;
    int n = blockIdx.x * 8 + warp;
    const float* wr = wcls + (size_t)n * C_;
    float s = 0.f;
    #pragma unroll 6
    for (int c = lane * 4; c < C_; c += 128) {
        float4 wv = *(const float4*)(wr + c);
        float4 fv = *(const float4*)(sf + c);
        s = fmaf(wv.x, fv.x, s);
        s = fmaf(wv.y, fv.y, s);
        s = fmaf(wv.z, fv.z, s);
        s = fmaf(wv.w, fv.w, s);
    }
    #pragma unroll
    for (int o = 16; o; o >>= 1) s += __shfl_xor_sync(0xffffffffu, s, o);
    if (lane == 0) scores[b * NC_ + n] = s;
}

// ---------------------------------------------------------------------------
extern "C" void kernel_launch(void* const* d_in, const int* in_sizes, int n_in,
                              void* d_out, int out_size) {
    const float* x    = (const float*)d_in[0];   // (B,C,H,W)
    const float* wl   = (const float*)d_in[1];   // (K,C)
    const float* mod  = (const float*)d_in[2];   // (1,C,K)
    const float* wcls = (const float*)d_in[3];   // (NC,C)
    float* out    = (float*)d_out;
    float* afm    = out;
    float* scores = out + OFF_SCORES;
    float* maps   = out + OFF_MAPS;
    float* attn   = out + OFF_ATTN;

    const int MAPS_SMEM = (C_ * 12 + 16 * 64 * 6 * 2) * 4;   // 196608 B
    cudaFuncSetAttribute(maps_kernel,
                         cudaFuncAttributeMaxDynamicSharedMemorySize, MAPS_SMEM);

    asq_kernel<<<K_, 256>>>(wl);
    dummy_kernel<<<1, 32>>>();
    maps_kernel<<<148, 512, MAPS_SMEM>>>(x, wl, maps);
    feat_kernel<<<dim3(24, B_), 256>>>(x, maps, mod, afm, attn);  // launch #4 -> profiled
    score_kernel<<<dim3(25, B_), 256>>>(wcls, scores);
}